// round 15
// baseline (speedup 1.0000x reference)
#include <cuda_runtime.h>
#include <math.h>
#include <stdint.h>

// ---------------- problem constants ----------------
#define NB     2
#define DIM    2048
#define SEQ    128
#define ALEN   1536
#define TLEN   512
#define HQN    16
#define HKVN   4
#define HDN    128
#define HCN    16
#define HDCN   128
#define FFN    8192
#define NLAYER 2
#define GRP    (HQN / HKVN)
#define NEGV   (-30000.0f)
#define EPSV   (1e-5f)

// ---------------- device scratch ----------------
__device__ float g_x[NB * DIM * SEQ];
__device__ float g_h[NB * DIM * SEQ];
__device__ float g_q[NB * HQN * HDN * SEQ];
__device__ float g_k[NB * HKVN * HDN * SEQ];
__device__ float g_v[NB * HKVN * HDN * SEQ];
__device__ float g_key[NB * HKVN * ALEN * HDN];
__device__ float g_val[NB * HKVN * HDN * ALEN];
__device__ float g_scores[NB * HQN * ALEN * SEQ];
__device__ float g_attn[NB * HQN * HDN * SEQ];
__device__ float g_cscores[NB * HCN * TLEN * SEQ];
__device__ float g_gu[NB * 2 * FFN * SEQ];
__device__ float g_gate[NB * FFN * SEQ];
__device__ float g_part[8388608];

// ---------------- helpers ----------------
__device__ __forceinline__ uint32_t f2tf(float f) {
    uint32_t u;
    asm("cvt.rna.tf32.f32 %0, %1;" : "=r"(u) : "f"(f));
    return u;
}
__device__ __forceinline__ void mma_tf32(float* c, const uint32_t* a, const uint32_t* b) {
    asm volatile(
        "mma.sync.aligned.m16n8k8.row.col.f32.tf32.tf32.f32 "
        "{%0,%1,%2,%3}, {%4,%5,%6,%7}, {%8,%9}, {%0,%1,%2,%3};\n"
        : "+f"(c[0]), "+f"(c[1]), "+f"(c[2]), "+f"(c[3])
        : "r"(a[0]), "r"(a[1]), "r"(a[2]), "r"(a[3]), "r"(b[0]), "r"(b[1]));
}

// ================================================================
// Core mainloop (BM=128, BK=16, 8 warps, double-buffered)
// ================================================================
#define GEMM_CORE(A_LDG_TN, A_LDG_NN, MODE_TN)                                     \
    float acc[4][4][4] = {};                                                       \
    float4 a0, a1, b0, b1;                                                         \
    {                                                                              \
        int kAbs = k0;                                                             \
        if (MODE_TN) { A_LDG_TN; } else { A_LDG_NN; }                              \
        b0 = *(const float4*)&Bb[(long)(kAbs + rA) * ldb + cA];                    \
        b1 = *(const float4*)&Bb[(long)(kAbs + rA + 8) * ldb + cA];                \
    }                                                                              \
    if (MODE_TN) {                                                                 \
        As[0][rA][cA + 0] = f2tf(a0.x); As[0][rA][cA + 1] = f2tf(a0.y);            \
        As[0][rA][cA + 2] = f2tf(a0.z); As[0][rA][cA + 3] = f2tf(a0.w);            \
        As[0][rA + 8][cA + 0] = f2tf(a1.x); As[0][rA + 8][cA + 1] = f2tf(a1.y);    \
        As[0][rA + 8][cA + 2] = f2tf(a1.z); As[0][rA + 8][cA + 3] = f2tf(a1.w);    \
    } else {                                                                       \
        As[0][kA + 0][mA] = f2tf(a0.x); As[0][kA + 1][mA] = f2tf(a0.y);            \
        As[0][kA + 2][mA] = f2tf(a0.z); As[0][kA + 3][mA] = f2tf(a0.w);            \
        As[0][kA + 0][mA + 64] = f2tf(a1.x); As[0][kA + 1][mA + 64] = f2tf(a1.y);  \
        As[0][kA + 2][mA + 64] = f2tf(a1.z); As[0][kA + 3][mA + 64] = f2tf(a1.w);  \
    }                                                                              \
    Bs[0][rA][cA + 0] = f2tf(b0.x); Bs[0][rA][cA + 1] = f2tf(b0.y);                \
    Bs[0][rA][cA + 2] = f2tf(b0.z); Bs[0][rA][cA + 3] = f2tf(b0.w);                \
    Bs[0][rA + 8][cA + 0] = f2tf(b1.x); Bs[0][rA + 8][cA + 1] = f2tf(b1.y);        \
    Bs[0][rA + 8][cA + 2] = f2tf(b1.z); Bs[0][rA + 8][cA + 3] = f2tf(b1.w);        \
    __syncthreads();                                                               \
    if (nT > 1) {                                                                  \
        int kAbs = k0 + 16;                                                        \
        if (MODE_TN) { A_LDG_TN; } else { A_LDG_NN; }                              \
        b0 = *(const float4*)&Bb[(long)(kAbs + rA) * ldb + cA];                    \
        b1 = *(const float4*)&Bb[(long)(kAbs + rA + 8) * ldb + cA];                \
    }                                                                              \
    for (int t = 0; t < nT; t++) {                                                 \
        const int cur = t & 1;                                                     \
        _Pragma("unroll")                                                          \
        for (int kh = 0; kh < 2; kh++) {                                           \
            const int kb = kh * 8;                                                 \
            uint32_t aF[4][4], bF[4][2];                                           \
            _Pragma("unroll")                                                      \
            for (int i = 0; i < 4; i++) {                                          \
                int r0 = wm + i * 16 + gid;                                        \
                aF[i][0] = As[cur][kb + tig][r0];                                  \
                aF[i][1] = As[cur][kb + tig][r0 + 8];                              \
                aF[i][2] = As[cur][kb + tig + 4][r0];                              \
                aF[i][3] = As[cur][kb + tig + 4][r0 + 8];                          \
            }                                                                      \
            _Pragma("unroll")                                                      \
            for (int j = 0; j < 4; j++) {                                          \
                int c0 = wn + j * 8 + gid;                                         \
                bF[j][0] = Bs[cur][kb + tig][c0];                                  \
                bF[j][1] = Bs[cur][kb + tig + 4][c0];                              \
            }                                                                      \
            _Pragma("unroll")                                                      \
            for (int i = 0; i < 4; i++)                                            \
                _Pragma("unroll")                                                  \
                for (int j = 0; j < 4; j++)                                        \
                    mma_tf32(acc[i][j], aF[i], bF[j]);                             \
        }                                                                          \
        if (t + 1 < nT) {                                                          \
            const int nxt = 1 - cur;                                               \
            if (MODE_TN) {                                                         \
                As[nxt][rA][cA + 0] = f2tf(a0.x); As[nxt][rA][cA + 1] = f2tf(a0.y);\
                As[nxt][rA][cA + 2] = f2tf(a0.z); As[nxt][rA][cA + 3] = f2tf(a0.w);\
                As[nxt][rA + 8][cA + 0] = f2tf(a1.x); As[nxt][rA + 8][cA + 1] = f2tf(a1.y);\
                As[nxt][rA + 8][cA + 2] = f2tf(a1.z); As[nxt][rA + 8][cA + 3] = f2tf(a1.w);\
            } else {                                                               \
                As[nxt][kA + 0][mA] = f2tf(a0.x); As[nxt][kA + 1][mA] = f2tf(a0.y);\
                As[nxt][kA + 2][mA] = f2tf(a0.z); As[nxt][kA + 3][mA] = f2tf(a0.w);\
                As[nxt][kA + 0][mA + 64] = f2tf(a1.x); As[nxt][kA + 1][mA + 64] = f2tf(a1.y);\
                As[nxt][kA + 2][mA + 64] = f2tf(a1.z); As[nxt][kA + 3][mA + 64] = f2tf(a1.w);\
            }                                                                      \
            Bs[nxt][rA][cA + 0] = f2tf(b0.x); Bs[nxt][rA][cA + 1] = f2tf(b0.y);    \
            Bs[nxt][rA][cA + 2] = f2tf(b0.z); Bs[nxt][rA][cA + 3] = f2tf(b0.w);    \
            Bs[nxt][rA + 8][cA + 0] = f2tf(b1.x); Bs[nxt][rA + 8][cA + 1] = f2tf(b1.y);\
            Bs[nxt][rA + 8][cA + 2] = f2tf(b1.z); Bs[nxt][rA + 8][cA + 3] = f2tf(b1.w);\
            if (t + 2 < nT) {                                                      \
                int kAbs = k0 + (t + 2) * 16;                                      \
                if (MODE_TN) { A_LDG_TN; } else { A_LDG_NN; }                      \
                b0 = *(const float4*)&Bb[(long)(kAbs + rA) * ldb + cA];            \
                b1 = *(const float4*)&Bb[(long)(kAbs + rA + 8) * ldb + cA];        \
            }                                                                      \
        }                                                                          \
        __syncthreads();                                                           \
    }

#define A_TN_STD \
    a0 = *(const float4*)&Ab[(long)(kAbs + rA) * lda + bm + cA]; \
    a1 = *(const float4*)&Ab[(long)(kAbs + rA + 8) * lda + bm + cA];
#define A_NN_STD \
    a0 = *(const float4*)&Ab[(long)(bm + mA) * lda + kAbs + kA]; \
    a1 = *(const float4*)&Ab[(long)(bm + mA + 64) * lda + kAbs + kA];

// ---------------- generic GEMM with device-side mask shaping ----------------
__global__ __launch_bounds__(256, 2) void gemm_mma(
    const float* __restrict__ A, const float* __restrict__ Bm, float* __restrict__ C,
    int K, int M, int lda, int ldb, int ldc,
    long strideA, int aDiv, long strideB, long strideC,
    int accum, int modeTN, int split, float* __restrict__ part,
    const int* __restrict__ limPtr, int limMode)
{
    __shared__ uint32_t As[2][16][136];
    __shared__ uint32_t Bs[2][16][136];

    const int z  = blockIdx.z;
    const int ks = blockIdx.y;
    const int bm = blockIdx.x * 128;
    const int kChunk = K / split;
    const int k0 = ks * kChunk;
    int nT = kChunk / 16;

    if (limMode == 1) {
        int lim = limPtr[0] + SEQ; if (lim > M) lim = M;
        if (bm >= lim) return;
    } else if (limMode == 2) {
        int lim = limPtr[z / HCN];
        if (bm >= lim) return;
    } else if (limMode == 3) {
        int kl = limPtr[0] + SEQ; if (kl > K) kl = K;
        int e = (kl - k0 + 15) >> 4;
        if (e <= 0) return;
        if (e < nT) nT = e;
    } else if (limMode == 4) {
        int kl = limPtr[z / HCN]; if (kl > K) kl = K;
        int e = (kl - k0 + 15) >> 4;
        if (e <= 0) return;
        if (e < nT) nT = e;
    }

    const float* Ab = A + (long)(z / aDiv) * strideA;
    const float* Bb = Bm + (long)z * strideB;

    const int tid  = threadIdx.x;
    const int warp = tid >> 5, lane = tid & 31;
    const int wm = (warp & 1) * 64;
    const int wn = (warp >> 1) * 32;
    const int gid = lane >> 2, tig = lane & 3;

    const int rA = tid >> 5;
    const int cA = (tid & 31) * 4;
    const int mA = tid >> 2;
    const int kA = (tid & 3) * 4;

    GEMM_CORE(A_TN_STD, A_NN_STD, modeTN)

    if (split == 1) {
        float* Cb = C + (long)z * strideC;
        #pragma unroll
        for (int i = 0; i < 4; i++) {
            int row = bm + wm + i * 16 + gid;
            #pragma unroll
            for (int j = 0; j < 4; j++) {
                int col = wn + j * 8 + 2 * tig;
                long i0 = (long)row * ldc + col;
                long i1 = (long)(row + 8) * ldc + col;
                if (accum) {
                    Cb[i0]     += acc[i][j][0];
                    Cb[i0 + 1] += acc[i][j][1];
                    Cb[i1]     += acc[i][j][2];
                    Cb[i1 + 1] += acc[i][j][3];
                } else {
                    Cb[i0]     = acc[i][j][0];
                    Cb[i0 + 1] = acc[i][j][1];
                    Cb[i1]     = acc[i][j][2];
                    Cb[i1 + 1] = acc[i][j][3];
                }
            }
        }
    } else {
        float* Pb = part + ((long)(z * split + ks) * M) * 128;
        #pragma unroll
        for (int i = 0; i < 4; i++) {
            int row = bm + wm + i * 16 + gid;
            #pragma unroll
            for (int j = 0; j < 4; j++) {
                int col = wn + j * 8 + 2 * tig;
                long i0 = (long)row * 128 + col;
                long i1 = (long)(row + 8) * 128 + col;
                Pb[i0]     = acc[i][j][0];
                Pb[i0 + 1] = acc[i][j][1];
                Pb[i1]     = acc[i][j][2];
                Pb[i1 + 1] = acc[i][j][3];
            }
        }
    }
}

// ---------------- fused multi-weight TN GEMM (qkv / gate+up) ----------------
__global__ __launch_bounds__(256, 2) void gemm_mma_multi(
    const float* __restrict__ A0, int lda0, int mEnd0,
    const float* __restrict__ A1, int lda1, int mEnd1,
    const float* __restrict__ A2, int lda2,
    const float* __restrict__ Bm, float* __restrict__ C,
    int K, int M, int ldb, long strideB, long strideC, float* __restrict__ part)
{
    __shared__ uint32_t As[2][16][136];
    __shared__ uint32_t Bs[2][16][136];

    const int z  = blockIdx.z;
    const int ks = blockIdx.y;
    const int split = gridDim.y;
    const int bmG = blockIdx.x * 128;
    const int kChunk = K / split;
    const int k0 = ks * kChunk;
    int nT = kChunk / 16;

    const float* Ab;
    int lda, bm;
    if (bmG < mEnd0)      { Ab = A0; lda = lda0; bm = bmG; }
    else if (bmG < mEnd1) { Ab = A1; lda = lda1; bm = bmG - mEnd0; }
    else                  { Ab = A2; lda = lda2; bm = bmG - mEnd1; }
    const float* Bb = Bm + (long)z * strideB;

    const int tid  = threadIdx.x;
    const int warp = tid >> 5, lane = tid & 31;
    const int wm = (warp & 1) * 64;
    const int wn = (warp >> 1) * 32;
    const int gid = lane >> 2, tig = lane & 3;

    const int rA = tid >> 5;
    const int cA = (tid & 31) * 4;
    const int mA = tid >> 2;
    const int kA = (tid & 3) * 4;

    GEMM_CORE(A_TN_STD, A_NN_STD, 1)

    if (split == 1) {
        float* Cb = C + (long)z * strideC;
        #pragma unroll
        for (int i = 0; i < 4; i++) {
            int row = bmG + wm + i * 16 + gid;
            #pragma unroll
            for (int j = 0; j < 4; j++) {
                int col = wn + j * 8 + 2 * tig;
                *(float2*)&Cb[(long)row * 128 + col] =
                    make_float2(acc[i][j][0], acc[i][j][1]);
                *(float2*)&Cb[(long)(row + 8) * 128 + col] =
                    make_float2(acc[i][j][2], acc[i][j][3]);
            }
        }
    } else {
        float* Pb = part + ((long)(z * split + ks) * M) * 128;
        #pragma unroll
        for (int i = 0; i < 4; i++) {
            int row = bmG + wm + i * 16 + gid;
            #pragma unroll
            for (int j = 0; j < 4; j++) {
                int col = wn + j * 8 + 2 * tig;
                *(float2*)&Pb[(long)row * 128 + col] =
                    make_float2(acc[i][j][0], acc[i][j][1]);
                *(float2*)&Pb[(long)(row + 8) * 128 + col] =
                    make_float2(acc[i][j][2], acc[i][j][3]);
            }
        }
    }
}

// deterministic split-K reduction; chunk-clamped for K-limited PV GEMMs
__global__ void reduce_split(const float* __restrict__ part, float* __restrict__ C,
                             long MN, int split, int accum, long total,
                             const int* __restrict__ limPtr, int limMode, int kChunk) {
    long i4 = (long)blockIdx.x * blockDim.x + threadIdx.x;
    long total4 = total >> 2;
    if (i4 >= total4) return;
    long MN4 = MN >> 2;
    long zi = i4 / MN4, mn = i4 % MN4;
    int splitEff = split;
    if (limMode == 3) {
        int lim = limPtr[0] + SEQ;
        int c = (lim + kChunk - 1) / kChunk;
        if (c < 1) c = 1;
        if (c < splitEff) splitEff = c;
    } else if (limMode == 4) {
        int lim = limPtr[(int)(zi / HCN)];
        int c = (lim + kChunk - 1) / kChunk;
        if (c < 1) c = 1;
        if (c < splitEff) splitEff = c;
    }
    const float4* p4 = (const float4*)part;
    float4* c4 = (float4*)C;
    float4 s;
    if (accum) s = c4[i4];
    else { s.x = 0.f; s.y = 0.f; s.z = 0.f; s.w = 0.f; }
    for (int k = 0; k < splitEff; k++) {
        float4 v = p4[(zi * (long)split + k) * MN4 + mn];
        s.x += v.x; s.y += v.y; s.z += v.z; s.w += v.w;
    }
    c4[i4] = s;
}

// ---------------- fused qkv reduce + RoPE (wide grid, SPLIT=4) ----------------
__global__ void reduce_qkv_rope(const float* __restrict__ part,
                                float* __restrict__ q, float* __restrict__ k,
                                float* __restrict__ v, const int* __restrict__ positions) {
    const int SPLIT = 4;
    int idx = blockIdx.x * blockDim.x + threadIdx.x;
    const int nA = NB * 20 * 64 * 32;
    const int nB = NB * 512 * 32;
    if (idx >= nA + nB) return;
    const float4* p4 = (const float4*)part;

    if (idx < nA) {
        int t = idx;
        int s4 = t & 31; t >>= 5;
        int i  = t & 63; t >>= 6;
        int hh = t % 20;
        int b  = t / 20;
        int row1;
        float4* out;
        long orow;
        if (hh < 16) { row1 = hh * 128 + i; out = (float4*)q; orow = (long)b * 2048 + row1; }
        else { int kh = hh - 16; row1 = 2048 + kh * 128 + i; out = (float4*)k; orow = (long)b * 512 + kh * 128 + i; }
        int row2 = row1 + 64;

        float4 x1 = {0.f, 0.f, 0.f, 0.f}, x2 = {0.f, 0.f, 0.f, 0.f};
        #pragma unroll 1
        for (int ks = 0; ks < SPLIT; ks++) {
            float4 a = p4[((long)(b * SPLIT + ks) * 3072 + row1) * 32 + s4];
            float4 c = p4[((long)(b * SPLIT + ks) * 3072 + row2) * 32 + s4];
            x1.x += a.x; x1.y += a.y; x1.z += a.z; x1.w += a.w;
            x2.x += c.x; x2.y += c.y; x2.z += c.z; x2.w += c.w;
        }
        float invf = powf(10000.0f, -(float)i / 64.0f);
        float y1[4], y2[4];
        const float* e1 = (const float*)&x1;
        const float* e2 = (const float*)&x2;
        #pragma unroll
        for (int e = 0; e < 4; e++) {
            int s = s4 * 4 + e;
            float pos = (float)positions[b * SEQ + s];
            float sn, cs;
            sincosf(pos * invf, &sn, &cs);
            y1[e] = e1[e] * cs - e2[e] * sn;
            y2[e] = e2[e] * cs + e1[e] * sn;
        }
        out[orow * 32 + s4] = make_float4(y1[0], y1[1], y1[2], y1[3]);
        out[(orow + 64) * 32 + s4] = make_float4(y2[0], y2[1], y2[2], y2[3]);
    } else {
        int j = idx - nA;
        int s4 = j & 31;
        int row = (j >> 5) % 512;
        int b = j / (512 * 32);
        float4 s = {0.f, 0.f, 0.f, 0.f};
        #pragma unroll 1
        for (int ks = 0; ks < SPLIT; ks++) {
            float4 a = p4[((long)(b * SPLIT + ks) * 3072 + 2560 + row) * 32 + s4];
            s.x += a.x; s.y += a.y; s.z += a.z; s.w += a.w;
        }
        ((float4*)v)[((long)b * 512 + row) * 32 + s4] = s;
    }
}

// ---------------- fused cq reduce + RoPE (SPLIT=8) ----------------
__global__ void reduce_rope_q(const float* __restrict__ part, float* __restrict__ q,
                              const int* __restrict__ positions) {
    const int SPLIT = 8;
    int idx = blockIdx.x * blockDim.x + threadIdx.x;
    if (idx >= NB * 16 * 64 * 32) return;
    int s4 = idx & 31;
    int i  = (idx >> 5) & 63;
    int h  = (idx >> 11) & 15;
    int b  = idx >> 15;
    int row1 = h * 128 + i;
    int row2 = row1 + 64;
    const float4* p4 = (const float4*)part;

    float4 x1 = {0.f, 0.f, 0.f, 0.f}, x2 = {0.f, 0.f, 0.f, 0.f};
    #pragma unroll 1
    for (int ks = 0; ks < SPLIT; ks++) {
        float4 a = p4[((long)(b * SPLIT + ks) * 2048 + row1) * 32 + s4];
        float4 c = p4[((long)(b * SPLIT + ks) * 2048 + row2) * 32 + s4];
        x1.x += a.x; x1.y += a.y; x1.z += a.z; x1.w += a.w;
        x2.x += c.x; x2.y += c.y; x2.z += c.z; x2.w += c.w;
    }
    float invf = powf(10000.0f, -(float)i / 64.0f);
    float y1[4], y2[4];
    const float* e1 = (const float*)&x1;
    const float* e2 = (const float*)&x2;
    #pragma unroll
    for (int e = 0; e < 4; e++) {
        int s = s4 * 4 + e;
        float pos = (float)positions[b * SEQ + s];
        float sn, cs;
        sincosf(pos * invf, &sn, &cs);
        y1[e] = e1[e] * cs - e2[e] * sn;
        y2[e] = e2[e] * cs + e1[e] * sn;
    }
    float4* out = (float4*)q;
    long orow = (long)b * 2048 + row1;
    out[orow * 32 + s4] = make_float4(y1[0], y1[1], y1[2], y1[3]);
    out[(orow + 64) * 32 + s4] = make_float4(y2[0], y2[1], y2[2], y2[3]);
}

// ---------------- RMSNorm (optionally also copying src into xkeep) ----------------
__global__ void rmsnorm_kernel(const float* __restrict__ x, const float* __restrict__ w,
                               float* __restrict__ out, float* __restrict__ xkeep) {
    int s = blockIdx.x * 32 + threadIdx.x;
    int b = blockIdx.y;
    const float* xb = x + (long)b * DIM * SEQ;
    float* ob = out + (long)b * DIM * SEQ;
    float* kb = xkeep ? xkeep + (long)b * DIM * SEQ : 0;
    float ss = 0.0f;
    for (int d = threadIdx.y; d < DIM; d += 8) {
        float v = xb[d * SEQ + s];
        if (kb) kb[d * SEQ + s] = v;
        ss += v * v;
    }
    __shared__ float red[8][33];
    red[threadIdx.y][threadIdx.x] = ss;
    __syncthreads();
    if (threadIdx.y == 0) {
        float tot = 0.0f;
        #pragma unroll
        for (int i = 0; i < 8; i++) tot += red[i][threadIdx.x];
        red[0][threadIdx.x] = rsqrtf(tot / (float)DIM + EPSV);
    }
    __syncthreads();
    float inv = red[0][threadIdx.x];
    for (int d = threadIdx.y; d < DIM; d += 8) {
        ob[d * SEQ + s] = xb[d * SEQ + s] * inv * w[d];
    }
}

// ---------------- merge k,v into scratch; constant-divisor indexing + window skip ----------------
__global__ void update_kv(const float* __restrict__ kc, const float* __restrict__ knew,
                          float* __restrict__ keybuf,
                          const float* __restrict__ vc, const float* __restrict__ vnew,
                          float* __restrict__ valbuf, const int* __restrict__ wptr) {
    int idx = blockIdx.x * blockDim.x + threadIdx.x;
    const int total = NB * HKVN * ALEN * HDN;
    if (idx >= total * 2) return;
    int w = wptr[0];
    int aLim = w + SEQ; if (aLim > ALEN) aLim = ALEN;
    int aCopy = (aLim + 127) & ~127; if (aCopy > ALEN) aCopy = ALEN;
    if (idx < total) {
        int d = idx % HDN;
        int a = (idx / HDN) % ALEN;
        if (a >= aCopy) return;
        int kh = (idx / (HDN * ALEN)) % HKVN;
        int b = idx / (HDN * ALEN * HKVN);
        float v;
        if (a >= w && a < w + SEQ) {
            v = knew[(((long)b * HKVN + kh) * HDN + d) * SEQ + (a - w)];
        } else {
            v = kc[idx];
        }
        keybuf[idx] = v;
    } else {
        int i = idx - total;
        int a = i % ALEN;
        if (a >= aCopy) return;
        int d = (i / ALEN) % HDN;
        int kh = (i / (ALEN * HDN)) % HKVN;
        int b = i / (ALEN * HDN * HKVN);
        float v;
        if (a >= w && a < w + SEQ) {
            v = vnew[(((long)b * HKVN + kh) * HDN + d) * SEQ + (a - w)];
        } else {
            v = vc[i];
        }
        valbuf[i] = v;
    }
}

// ---------------- self-attn softmax with window limit ----------------
__global__ void sa_softmax(float* __restrict__ sc, const int* __restrict__ wptr, float scale) {
    int s = blockIdx.x * 32 + threadIdx.x;
    int z = blockIdx.y;
    int w = wptr[0];
    int aLim = w + SEQ; if (aLim > ALEN) aLim = ALEN;
    int aZ = (aLim + 15) & ~15; if (aZ > ALEN) aZ = ALEN;
    float* p = sc + (long)z * ALEN * SEQ;
    __shared__ float red[8][33];

    float mx = -3.0e38f;
    for (int a = threadIdx.y; a < aLim; a += 8) {
        float v = p[(long)a * SEQ + s] * scale;
        if (a > w + s) v += NEGV;
        p[(long)a * SEQ + s] = v;
        mx = fmaxf(mx, v);
    }
    red[threadIdx.y][threadIdx.x] = mx;
    __syncthreads();
    if (threadIdx.y == 0) {
        float m = red[0][threadIdx.x];
        #pragma unroll
        for (int i = 1; i < 8; i++) m = fmaxf(m, red[i][threadIdx.x]);
        red[0][threadIdx.x] = m;
    }
    __syncthreads();
    mx = red[0][threadIdx.x];
    __syncthreads();

    float sum = 0.0f;
    for (int a = threadIdx.y; a < aLim; a += 8) {
        float e = expf(p[(long)a * SEQ + s] - mx);
        p[(long)a * SEQ + s] = e;
        sum += e;
    }
    red[threadIdx.y][threadIdx.x] = sum;
    __syncthreads();
    if (threadIdx.y == 0) {
        float t = red[0][threadIdx.x];
        #pragma unroll
        for (int i = 1; i < 8; i++) t += red[i][threadIdx.x];
        red[0][threadIdx.x] = 1.0f / t;
    }
    __syncthreads();
    float rinv = red[0][threadIdx.x];
    for (int a = threadIdx.y; a < aLim; a += 8) {
        p[(long)a * SEQ + s] *= rinv;
    }
    for (int a = aLim + threadIdx.y; a < aZ; a += 8) {
        p[(long)a * SEQ + s] = 0.0f;
    }
}

// ---------------- cross-attn softmax with length limit ----------------
__global__ void ca_softmax(float* __restrict__ sc, const int* __restrict__ enc, float scale) {
    int s = blockIdx.x * 32 + threadIdx.x;
    int z = blockIdx.y;
    int b = z / HCN;
    int len = enc[b]; if (len > TLEN) len = TLEN;
    int tZ = (len + 15) & ~15; if (tZ > TLEN) tZ = TLEN;
    float* p = sc + (long)z * TLEN * SEQ;
    __shared__ float red[8][33];

    float mx = -3.0e38f;
    for (int t = threadIdx.y; t < len; t += 8) {
        float v = p[(long)t * SEQ + s] * scale;
        p[(long)t * SEQ + s] = v;
        mx = fmaxf(mx, v);
    }
    red[threadIdx.y][threadIdx.x] = mx;
    __syncthreads();
    if (threadIdx.y == 0) {
        float m = red[0][threadIdx.x];
        #pragma unroll
        for (int i = 1; i < 8; i++) m = fmaxf(m, red[i][threadIdx.x]);
        red[0][threadIdx.x] = m;
    }
    __syncthreads();
    mx = red[0][threadIdx.x];
    __syncthreads();

    float sum = 0.0f;
    for (int t = threadIdx.y; t < len; t += 8) {
        float e = expf(p[(long)t * SEQ + s] - mx);
        p[(long)t * SEQ + s] = e;
        sum += e;
    }
    red[threadIdx.y][threadIdx.x] = sum;
    __syncthreads();
    if (threadIdx.y == 0) {
        float t = red[0][threadIdx.x];
        #pragma unroll
        for (int i = 1; i < 8; i++) t += red[i][threadIdx.x];
        red[0][threadIdx.x] = 1.0f / t;
    }
    __syncthreads();
    float rinv = red[0][threadIdx.x];
    for (int t = threadIdx.y; t < len; t += 8) {
        p[(long)t * SEQ + s] *= rinv;
    }
    for (int t = len + threadIdx.y; t < tZ; t += 8) {
        p[(long)t * SEQ + s] = 0.0f;
    }
}

__global__ void silu_mul_gu(const float* __restrict__ gu, float* __restrict__ out) {
    int i = blockIdx.x * blockDim.x + threadIdx.x;
    const int per = FFN * SEQ;
    if (i >= NB * per) return;
    int b = i / per, r = i % per;
    float g = gu[(long)b * 2 * per + r];
    float u = gu[(long)b * 2 * per + per + r];
    out[i] = (g / (1.0f + expf(-g))) * u;
}

// ---------------- host orchestration ----------------
extern "C" void kernel_launch(void* const* d_in, const int* in_sizes, int n_in,
                              void* d_out, int out_size) {
    const float* x_in     = (const float*)d_in[0];
    const int*   positions= (const int*)d_in[1];
    const int*   kvw      = (const int*)d_in[2];
    const int*   enc_len  = (const int*)d_in[4];
    const float* q_w      = (const float*)d_in[5];
    const float* k_w      = (const float*)d_in[6];
    const float* v_w      = (const float*)d_in[7];
    const float* o_w      = (const float*)d_in[8];
    const float* cq_w     = (const float*)d_in[9];
    const float* co_w     = (const float*)d_in[10];
    const float* sa_norm  = (const float*)d_in[11];
    const float* ca_norm  = (const float*)d_in[12];
    const float* mlp_norm = (const float*)d_in[13];
    const float* fin_norm = (const float*)d_in[14];
    const float* wg_w     = (const float*)d_in[15];
    const float* wu_w     = (const float*)d_in[16];
    const float* wd_w     = (const float*)d_in[17];
    const float* k_cache  = (const float*)d_in[18];
    const float* v_cache  = (const float*)d_in[19];
    const float* ck_cache = (const float*)d_in[20];
    const float* cv_cache = (const float*)d_in[21];

    float *px, *ph, *pq, *pk, *pv, *pkey, *pval, *psc, *pattn, *pcsc, *pgu, *pgate, *ppart;
    cudaGetSymbolAddress((void**)&px,    g_x);
    cudaGetSymbolAddress((void**)&ph,    g_h);
    cudaGetSymbolAddress((void**)&pq,    g_q);
    cudaGetSymbolAddress((void**)&pk,    g_k);
    cudaGetSymbolAddress((void**)&pv,    g_v);
    cudaGetSymbolAddress((void**)&pkey,  g_key);
    cudaGetSymbolAddress((void**)&pval,  g_val);
    cudaGetSymbolAddress((void**)&psc,   g_scores);
    cudaGetSymbolAddress((void**)&pattn, g_attn);
    cudaGetSymbolAddress((void**)&pcsc,  g_cscores);
    cudaGetSymbolAddress((void**)&pgu,   g_gu);
    cudaGetSymbolAddress((void**)&pgate, g_gate);
    cudaGetSymbolAddress((void**)&ppart, g_part);

    const float scale = 0.08838834764831845f;  // 1/sqrt(128)
    dim3 blk328(32, 8);

    for (int l = 0; l < NLAYER; l++) {
        long wOffD2  = (long)l * DIM * DIM;
        long wOffKV  = (long)l * DIM * (HKVN * HDN);
        long wOffFF  = (long)l * DIM * FFN;
        long wOffFFd = (long)l * FFN * DIM;
        long cOffK   = (long)l * NB * HCN * TLEN * HDCN;
        long cOffV   = (long)l * NB * HCN * HDCN * TLEN;

        // ---- self attention ----
        if (l == 0) {
            rmsnorm_kernel<<<dim3(SEQ / 32, NB), blk328>>>(x_in, sa_norm, ph, px);
        } else {
            rmsnorm_kernel<<<dim3(SEQ / 32, NB), blk328>>>(px, sa_norm + (long)l * DIM, ph, (float*)0);
        }

        // fused qkv: M=3072, split=4 -> 192 CTAs -> partials; fused reduce+rope
        gemm_mma_multi<<<dim3(24, 4, NB), 256>>>(
            q_w + wOffD2, 2048, 2048,
            k_w + wOffKV, 512, 2560,
            v_w + wOffKV, 512,
            ph, (float*)0, DIM, 3072, SEQ, (long)DIM * SEQ, 0, ppart);
        {
            int n = NB * 20 * 64 * 32 + NB * 512 * 32;
            reduce_qkv_rope<<<(n + 255) / 256, 256>>>(ppart, pq, pk, pv, positions);
        }
        {
            int n = 2 * NB * HKVN * ALEN * HDN;
            update_kv<<<(n + 255) / 256, 256>>>(
                k_cache + (long)l * NB * HKVN * ALEN * HDN, pk, pkey,
                v_cache + (long)l * NB * HKVN * HDN * ALEN, pv, pval, kvw);
        }

        // scores: NN split=1, skip fully-masked row tiles (mode 1)
        gemm_mma<<<dim3(12, 1, NB * HQN), 256>>>(pkey, pq, psc,
            HDN, ALEN, HDN, SEQ, SEQ, (long)ALEN * HDN, GRP, (long)HDN * SEQ, (long)ALEN * SEQ,
            0, 0, 1, ppart, kvw, 1);

        sa_softmax<<<dim3(SEQ / 32, NB * HQN), blk328>>>(psc, kvw, scale);

        // attn = val @ probs: split=16, K-clamped (mode 3)
        gemm_mma<<<dim3(1, 16, NB * HQN), 256>>>(pval, psc, pattn,
            ALEN, HDN, ALEN, SEQ, SEQ, (long)HDN * ALEN, GRP, (long)ALEN * SEQ, 0,
            0, 0, 16, ppart, kvw, 3);
        reduce_split<<<(32 * 128 * 128 / 4 + 255) / 256, 256>>>(ppart, pattn, 128L * 128, 16, 0, 32L * 128 * 128,
            kvw, 3, ALEN / 16);

        // o: split=8 -> 256 CTAs (full occ-2 wave)
        gemm_mma<<<dim3(16, 8, NB), 256>>>(o_w + wOffD2, pattn, px,
            HQN * HDN, DIM, DIM, SEQ, SEQ, 0, 1, (long)HQN * HDN * SEQ, 0, 0, 1, 8, ppart, kvw, 0);
        reduce_split<<<(NB * 2048 * 128 / 4 + 255) / 256, 256>>>(ppart, px, 2048L * 128, 8, 1, (long)NB * 2048 * 128,
            kvw, 0, 0);

        // ---- cross attention ----
        rmsnorm_kernel<<<dim3(SEQ / 32, NB), blk328>>>(px, ca_norm + (long)l * DIM, ph, (float*)0);

        // cq: split=8 -> partials; fused reduce+rope
        gemm_mma<<<dim3(16, 8, NB), 256>>>(cq_w + wOffD2, ph, pq,
            DIM, 2048, 2048, SEQ, SEQ, 0, 1, (long)DIM * SEQ, 0, 0, 1, 8, ppart, kvw, 0);
        {
            int n = NB * 16 * 64 * 32;
            reduce_rope_q<<<(n + 255) / 256, 256>>>(ppart, pq, positions);
        }

        // cscores: skip tiles beyond encoder length (mode 2)
        gemm_mma<<<dim3(4, 1, NB * HCN), 256>>>(ck_cache + cOffK, pq, pcsc,
            HDCN, TLEN, HDCN, SEQ, SEQ, (long)TLEN * HDCN, 1, (long)HDCN * SEQ, (long)TLEN * SEQ,
            0, 0, 1, ppart, enc_len, 2);

        ca_softmax<<<dim3(SEQ / 32, NB * HCN), blk328>>>(pcsc, enc_len, scale);

        // cattn: K-clamped at encoder length (mode 4)
        gemm_mma<<<dim3(1, 8, NB * HCN), 256>>>(cv_cache + cOffV, pcsc, pattn,
            TLEN, HDCN, TLEN, SEQ, SEQ, (long)HDCN * TLEN, 1, (long)TLEN * SEQ, 0,
            0, 0, 8, ppart, enc_len, 4);
        reduce_split<<<(32 * 128 * 128 / 4 + 255) / 256, 256>>>(ppart, pattn, 128L * 128, 8, 0, 32L * 128 * 128,
            enc_len, 4, TLEN / 8);

        // co: split=8
        gemm_mma<<<dim3(16, 8, NB), 256>>>(co_w + wOffD2, pattn, px,
            HCN * HDCN, DIM, DIM, SEQ, SEQ, 0, 1, (long)HCN * HDCN * SEQ, 0, 0, 1, 8, ppart, kvw, 0);
        reduce_split<<<(NB * 2048 * 128 / 4 + 255) / 256, 256>>>(ppart, px, 2048L * 128, 8, 1, (long)NB * 2048 * 128,
            kvw, 0, 0);

        // ---- MLP ----
        rmsnorm_kernel<<<dim3(SEQ / 32, NB), blk328>>>(px, mlp_norm + (long)l * DIM, ph, (float*)0);

        // fused gate+up: M=16384, split=1 -> 256 CTAs, DIRECT write
        gemm_mma_multi<<<dim3(128, 1, NB), 256>>>(
            wg_w + wOffFF, FFN, FFN,
            wu_w + wOffFF, FFN, 2 * FFN,
            wu_w + wOffFF, FFN,
            ph, pgu, DIM, 2 * FFN, SEQ, (long)DIM * SEQ, (long)2 * FFN * SEQ, ppart);
        {
            int n = NB * FFN * SEQ;
            silu_mul_gu<<<(n + 255) / 256, 256>>>(pgu, pgate);
        }
        // down: split=8 -> 256 CTAs
        gemm_mma<<<dim3(16, 8, NB), 256>>>(wd_w + wOffFFd, pgate, px,
            FFN, DIM, DIM, SEQ, SEQ, 0, 1, (long)FFN * SEQ, 0, 0, 1, 8, ppart, kvw, 0);
        reduce_split<<<(NB * 2048 * 128 / 4 + 255) / 256, 256>>>(ppart, px, 2048L * 128, 8, 1, (long)NB * 2048 * 128,
            kvw, 0, 0);
    }

    rmsnorm_kernel<<<dim3(SEQ / 32, NB), blk328>>>(px, fin_norm, (float*)d_out, (float*)0);
}

// round 16
// speedup vs baseline: 1.5077x; 1.5077x over previous
#include <cuda_runtime.h>
#include <math.h>
#include <stdint.h>

// ---------------- problem constants ----------------
#define NB     2
#define DIM    2048
#define SEQ    128
#define ALEN   1536
#define TLEN   512
#define HQN    16
#define HKVN   4
#define HDN    128
#define HCN    16
#define HDCN   128
#define FFN    8192
#define NLAYER 2
#define GRP    (HQN / HKVN)
#define NEGV   (-30000.0f)
#define EPSV   (1e-5f)

// ---------------- device scratch ----------------
__device__ float g_x[NB * DIM * SEQ];
__device__ float g_h[NB * DIM * SEQ];
__device__ float g_q[NB * HQN * HDN * SEQ];
__device__ float g_k[NB * HKVN * HDN * SEQ];
__device__ float g_v[NB * HKVN * HDN * SEQ];
__device__ float g_key[NB * HKVN * ALEN * HDN];
__device__ float g_val[NB * HKVN * HDN * ALEN];
__device__ float g_scores[NB * HQN * ALEN * SEQ];
__device__ float g_attn[NB * HQN * HDN * SEQ];
__device__ float g_cscores[NB * HCN * TLEN * SEQ];
__device__ float g_gu[NB * 2 * FFN * SEQ];
__device__ float g_gate[NB * FFN * SEQ];
__device__ float g_part[8388608];

// ---------------- helpers ----------------
__device__ __forceinline__ uint32_t f2tf(float f) {
    uint32_t u;
    asm("cvt.rna.tf32.f32 %0, %1;" : "=r"(u) : "f"(f));
    return u;
}
__device__ __forceinline__ void mma_tf32(float* c, const uint32_t* a, const uint32_t* b) {
    asm volatile(
        "mma.sync.aligned.m16n8k8.row.col.f32.tf32.tf32.f32 "
        "{%0,%1,%2,%3}, {%4,%5,%6,%7}, {%8,%9}, {%0,%1,%2,%3};\n"
        : "+f"(c[0]), "+f"(c[1]), "+f"(c[2]), "+f"(c[3])
        : "r"(a[0]), "r"(a[1]), "r"(a[2]), "r"(a[3]), "r"(b[0]), "r"(b[1]));
}

// ================================================================
// Core mainloop (BM=128, BK=16, 8 warps, double-buffered)
// ================================================================
#define GEMM_CORE(A_LDG_TN, A_LDG_NN, MODE_TN)                                     \
    float acc[4][4][4] = {};                                                       \
    float4 a0, a1, b0, b1;                                                         \
    {                                                                              \
        int kAbs = k0;                                                             \
        if (MODE_TN) { A_LDG_TN; } else { A_LDG_NN; }                              \
        b0 = *(const float4*)&Bb[(long)(kAbs + rA) * ldb + cA];                    \
        b1 = *(const float4*)&Bb[(long)(kAbs + rA + 8) * ldb + cA];                \
    }                                                                              \
    if (MODE_TN) {                                                                 \
        As[0][rA][cA + 0] = f2tf(a0.x); As[0][rA][cA + 1] = f2tf(a0.y);            \
        As[0][rA][cA + 2] = f2tf(a0.z); As[0][rA][cA + 3] = f2tf(a0.w);            \
        As[0][rA + 8][cA + 0] = f2tf(a1.x); As[0][rA + 8][cA + 1] = f2tf(a1.y);    \
        As[0][rA + 8][cA + 2] = f2tf(a1.z); As[0][rA + 8][cA + 3] = f2tf(a1.w);    \
    } else {                                                                       \
        As[0][kA + 0][mA] = f2tf(a0.x); As[0][kA + 1][mA] = f2tf(a0.y);            \
        As[0][kA + 2][mA] = f2tf(a0.z); As[0][kA + 3][mA] = f2tf(a0.w);            \
        As[0][kA + 0][mA + 64] = f2tf(a1.x); As[0][kA + 1][mA + 64] = f2tf(a1.y);  \
        As[0][kA + 2][mA + 64] = f2tf(a1.z); As[0][kA + 3][mA + 64] = f2tf(a1.w);  \
    }                                                                              \
    Bs[0][rA][cA + 0] = f2tf(b0.x); Bs[0][rA][cA + 1] = f2tf(b0.y);                \
    Bs[0][rA][cA + 2] = f2tf(b0.z); Bs[0][rA][cA + 3] = f2tf(b0.w);                \
    Bs[0][rA + 8][cA + 0] = f2tf(b1.x); Bs[0][rA + 8][cA + 1] = f2tf(b1.y);        \
    Bs[0][rA + 8][cA + 2] = f2tf(b1.z); Bs[0][rA + 8][cA + 3] = f2tf(b1.w);        \
    __syncthreads();                                                               \
    if (nT > 1) {                                                                  \
        int kAbs = k0 + 16;                                                        \
        if (MODE_TN) { A_LDG_TN; } else { A_LDG_NN; }                              \
        b0 = *(const float4*)&Bb[(long)(kAbs + rA) * ldb + cA];                    \
        b1 = *(const float4*)&Bb[(long)(kAbs + rA + 8) * ldb + cA];                \
    }                                                                              \
    for (int t = 0; t < nT; t++) {                                                 \
        const int cur = t & 1;                                                     \
        _Pragma("unroll")                                                          \
        for (int kh = 0; kh < 2; kh++) {                                           \
            const int kb = kh * 8;                                                 \
            uint32_t aF[4][4], bF[4][2];                                           \
            _Pragma("unroll")                                                      \
            for (int i = 0; i < 4; i++) {                                          \
                int r0 = wm + i * 16 + gid;                                        \
                aF[i][0] = As[cur][kb + tig][r0];                                  \
                aF[i][1] = As[cur][kb + tig][r0 + 8];                              \
                aF[i][2] = As[cur][kb + tig + 4][r0];                              \
                aF[i][3] = As[cur][kb + tig + 4][r0 + 8];                          \
            }                                                                      \
            _Pragma("unroll")                                                      \
            for (int j = 0; j < 4; j++) {                                          \
                int c0 = wn + j * 8 + gid;                                         \
                bF[j][0] = Bs[cur][kb + tig][c0];                                  \
                bF[j][1] = Bs[cur][kb + tig + 4][c0];                              \
            }                                                                      \
            _Pragma("unroll")                                                      \
            for (int i = 0; i < 4; i++)                                            \
                _Pragma("unroll")                                                  \
                for (int j = 0; j < 4; j++)                                        \
                    mma_tf32(acc[i][j], aF[i], bF[j]);                             \
        }                                                                          \
        if (t + 1 < nT) {                                                          \
            const int nxt = 1 - cur;                                               \
            if (MODE_TN) {                                                         \
                As[nxt][rA][cA + 0] = f2tf(a0.x); As[nxt][rA][cA + 1] = f2tf(a0.y);\
                As[nxt][rA][cA + 2] = f2tf(a0.z); As[nxt][rA][cA + 3] = f2tf(a0.w);\
                As[nxt][rA + 8][cA + 0] = f2tf(a1.x); As[nxt][rA + 8][cA + 1] = f2tf(a1.y);\
                As[nxt][rA + 8][cA + 2] = f2tf(a1.z); As[nxt][rA + 8][cA + 3] = f2tf(a1.w);\
            } else {                                                               \
                As[nxt][kA + 0][mA] = f2tf(a0.x); As[nxt][kA + 1][mA] = f2tf(a0.y);\
                As[nxt][kA + 2][mA] = f2tf(a0.z); As[nxt][kA + 3][mA] = f2tf(a0.w);\
                As[nxt][kA + 0][mA + 64] = f2tf(a1.x); As[nxt][kA + 1][mA + 64] = f2tf(a1.y);\
                As[nxt][kA + 2][mA + 64] = f2tf(a1.z); As[nxt][kA + 3][mA + 64] = f2tf(a1.w);\
            }                                                                      \
            Bs[nxt][rA][cA + 0] = f2tf(b0.x); Bs[nxt][rA][cA + 1] = f2tf(b0.y);    \
            Bs[nxt][rA][cA + 2] = f2tf(b0.z); Bs[nxt][rA][cA + 3] = f2tf(b0.w);    \
            Bs[nxt][rA + 8][cA + 0] = f2tf(b1.x); Bs[nxt][rA + 8][cA + 1] = f2tf(b1.y);\
            Bs[nxt][rA + 8][cA + 2] = f2tf(b1.z); Bs[nxt][rA + 8][cA + 3] = f2tf(b1.w);\
            if (t + 2 < nT) {                                                      \
                int kAbs = k0 + (t + 2) * 16;                                      \
                if (MODE_TN) { A_LDG_TN; } else { A_LDG_NN; }                      \
                b0 = *(const float4*)&Bb[(long)(kAbs + rA) * ldb + cA];            \
                b1 = *(const float4*)&Bb[(long)(kAbs + rA + 8) * ldb + cA];        \
            }                                                                      \
        }                                                                          \
        __syncthreads();                                                           \
    }

#define A_TN_STD \
    a0 = *(const float4*)&Ab[(long)(kAbs + rA) * lda + bm + cA]; \
    a1 = *(const float4*)&Ab[(long)(kAbs + rA + 8) * lda + bm + cA];
#define A_NN_STD \
    a0 = *(const float4*)&Ab[(long)(bm + mA) * lda + kAbs + kA]; \
    a1 = *(const float4*)&Ab[(long)(bm + mA + 64) * lda + kAbs + kA];

// ---------------- generic GEMM with device-side mask shaping ----------------
__global__ __launch_bounds__(256, 2) void gemm_mma(
    const float* __restrict__ A, const float* __restrict__ Bm, float* __restrict__ C,
    int K, int M, int lda, int ldb, int ldc,
    long strideA, int aDiv, long strideB, long strideC,
    int accum, int modeTN, int split, float* __restrict__ part,
    const int* __restrict__ limPtr, int limMode)
{
    __shared__ uint32_t As[2][16][136];
    __shared__ uint32_t Bs[2][16][136];

    const int z  = blockIdx.z;
    const int ks = blockIdx.y;
    const int bm = blockIdx.x * 128;
    const int kChunk = K / split;
    const int k0 = ks * kChunk;
    int nT = kChunk / 16;

    if (limMode == 1) {
        int lim = limPtr[0] + SEQ; if (lim > M) lim = M;
        if (bm >= lim) return;
    } else if (limMode == 2) {
        int lim = limPtr[z / HCN];
        if (bm >= lim) return;
    } else if (limMode == 3) {
        int kl = limPtr[0] + SEQ; if (kl > K) kl = K;
        int e = (kl - k0 + 15) >> 4;
        if (e <= 0) return;
        if (e < nT) nT = e;
    } else if (limMode == 4) {
        int kl = limPtr[z / HCN]; if (kl > K) kl = K;
        int e = (kl - k0 + 15) >> 4;
        if (e <= 0) return;
        if (e < nT) nT = e;
    }

    const float* Ab = A + (long)(z / aDiv) * strideA;
    const float* Bb = Bm + (long)z * strideB;

    const int tid  = threadIdx.x;
    const int warp = tid >> 5, lane = tid & 31;
    const int wm = (warp & 1) * 64;
    const int wn = (warp >> 1) * 32;
    const int gid = lane >> 2, tig = lane & 3;

    const int rA = tid >> 5;
    const int cA = (tid & 31) * 4;
    const int mA = tid >> 2;
    const int kA = (tid & 3) * 4;

    GEMM_CORE(A_TN_STD, A_NN_STD, modeTN)

    if (split == 1) {
        float* Cb = C + (long)z * strideC;
        #pragma unroll
        for (int i = 0; i < 4; i++) {
            int row = bm + wm + i * 16 + gid;
            #pragma unroll
            for (int j = 0; j < 4; j++) {
                int col = wn + j * 8 + 2 * tig;
                long i0 = (long)row * ldc + col;
                long i1 = (long)(row + 8) * ldc + col;
                if (accum) {
                    Cb[i0]     += acc[i][j][0];
                    Cb[i0 + 1] += acc[i][j][1];
                    Cb[i1]     += acc[i][j][2];
                    Cb[i1 + 1] += acc[i][j][3];
                } else {
                    Cb[i0]     = acc[i][j][0];
                    Cb[i0 + 1] = acc[i][j][1];
                    Cb[i1]     = acc[i][j][2];
                    Cb[i1 + 1] = acc[i][j][3];
                }
            }
        }
    } else {
        float* Pb = part + ((long)(z * split + ks) * M) * 128;
        #pragma unroll
        for (int i = 0; i < 4; i++) {
            int row = bm + wm + i * 16 + gid;
            #pragma unroll
            for (int j = 0; j < 4; j++) {
                int col = wn + j * 8 + 2 * tig;
                long i0 = (long)row * 128 + col;
                long i1 = (long)(row + 8) * 128 + col;
                Pb[i0]     = acc[i][j][0];
                Pb[i0 + 1] = acc[i][j][1];
                Pb[i1]     = acc[i][j][2];
                Pb[i1 + 1] = acc[i][j][3];
            }
        }
    }
}

// ---------------- fused multi-weight TN GEMM (qkv / gate+up) ----------------
__global__ __launch_bounds__(256, 2) void gemm_mma_multi(
    const float* __restrict__ A0, int lda0, int mEnd0,
    const float* __restrict__ A1, int lda1, int mEnd1,
    const float* __restrict__ A2, int lda2,
    const float* __restrict__ Bm, float* __restrict__ C,
    int K, int M, int ldb, long strideB, long strideC, float* __restrict__ part)
{
    __shared__ uint32_t As[2][16][136];
    __shared__ uint32_t Bs[2][16][136];

    const int z  = blockIdx.z;
    const int ks = blockIdx.y;
    const int split = gridDim.y;
    const int bmG = blockIdx.x * 128;
    const int kChunk = K / split;
    const int k0 = ks * kChunk;
    int nT = kChunk / 16;

    const float* Ab;
    int lda, bm;
    if (bmG < mEnd0)      { Ab = A0; lda = lda0; bm = bmG; }
    else if (bmG < mEnd1) { Ab = A1; lda = lda1; bm = bmG - mEnd0; }
    else                  { Ab = A2; lda = lda2; bm = bmG - mEnd1; }
    const float* Bb = Bm + (long)z * strideB;

    const int tid  = threadIdx.x;
    const int warp = tid >> 5, lane = tid & 31;
    const int wm = (warp & 1) * 64;
    const int wn = (warp >> 1) * 32;
    const int gid = lane >> 2, tig = lane & 3;

    const int rA = tid >> 5;
    const int cA = (tid & 31) * 4;
    const int mA = tid >> 2;
    const int kA = (tid & 3) * 4;

    GEMM_CORE(A_TN_STD, A_NN_STD, 1)

    if (split == 1) {
        float* Cb = C + (long)z * strideC;
        #pragma unroll
        for (int i = 0; i < 4; i++) {
            int row = bmG + wm + i * 16 + gid;
            #pragma unroll
            for (int j = 0; j < 4; j++) {
                int col = wn + j * 8 + 2 * tig;
                *(float2*)&Cb[(long)row * 128 + col] =
                    make_float2(acc[i][j][0], acc[i][j][1]);
                *(float2*)&Cb[(long)(row + 8) * 128 + col] =
                    make_float2(acc[i][j][2], acc[i][j][3]);
            }
        }
    } else {
        float* Pb = part + ((long)(z * split + ks) * M) * 128;
        #pragma unroll
        for (int i = 0; i < 4; i++) {
            int row = bmG + wm + i * 16 + gid;
            #pragma unroll
            for (int j = 0; j < 4; j++) {
                int col = wn + j * 8 + 2 * tig;
                *(float2*)&Pb[(long)row * 128 + col] =
                    make_float2(acc[i][j][0], acc[i][j][1]);
                *(float2*)&Pb[(long)(row + 8) * 128 + col] =
                    make_float2(acc[i][j][2], acc[i][j][3]);
            }
        }
    }
}

// deterministic split-K reduction; chunk-clamped for K-limited PV GEMMs
__global__ void reduce_split(const float* __restrict__ part, float* __restrict__ C,
                             long MN, int split, int accum, long total,
                             const int* __restrict__ limPtr, int limMode, int kChunk) {
    long i4 = (long)blockIdx.x * blockDim.x + threadIdx.x;
    long total4 = total >> 2;
    if (i4 >= total4) return;
    long MN4 = MN >> 2;
    long zi = i4 / MN4, mn = i4 % MN4;
    int splitEff = split;
    if (limMode == 3) {
        int lim = limPtr[0] + SEQ;
        int c = (lim + kChunk - 1) / kChunk;
        if (c < 1) c = 1;
        if (c < splitEff) splitEff = c;
    } else if (limMode == 4) {
        int lim = limPtr[(int)(zi / HCN)];
        int c = (lim + kChunk - 1) / kChunk;
        if (c < 1) c = 1;
        if (c < splitEff) splitEff = c;
    }
    const float4* p4 = (const float4*)part;
    float4* c4 = (float4*)C;
    float4 s;
    if (accum) s = c4[i4];
    else { s.x = 0.f; s.y = 0.f; s.z = 0.f; s.w = 0.f; }
    for (int k = 0; k < splitEff; k++) {
        float4 v = p4[(zi * (long)split + k) * MN4 + mn];
        s.x += v.x; s.y += v.y; s.z += v.z; s.w += v.w;
    }
    c4[i4] = s;
}

// ---------------- fused qkv reduce + RoPE (wide grid, SPLIT=4) ----------------
__global__ void reduce_qkv_rope(const float* __restrict__ part,
                                float* __restrict__ q, float* __restrict__ k,
                                float* __restrict__ v, const int* __restrict__ positions) {
    const int SPLIT = 4;
    int idx = blockIdx.x * blockDim.x + threadIdx.x;
    const int nA = NB * 20 * 64 * 32;
    const int nB = NB * 512 * 32;
    if (idx >= nA + nB) return;
    const float4* p4 = (const float4*)part;

    if (idx < nA) {
        int t = idx;
        int s4 = t & 31; t >>= 5;
        int i  = t & 63; t >>= 6;
        int hh = t % 20;
        int b  = t / 20;
        int row1;
        float4* out;
        long orow;
        if (hh < 16) { row1 = hh * 128 + i; out = (float4*)q; orow = (long)b * 2048 + row1; }
        else { int kh = hh - 16; row1 = 2048 + kh * 128 + i; out = (float4*)k; orow = (long)b * 512 + kh * 128 + i; }
        int row2 = row1 + 64;

        float4 x1 = {0.f, 0.f, 0.f, 0.f}, x2 = {0.f, 0.f, 0.f, 0.f};
        #pragma unroll 1
        for (int ks = 0; ks < SPLIT; ks++) {
            float4 a = p4[((long)(b * SPLIT + ks) * 3072 + row1) * 32 + s4];
            float4 c = p4[((long)(b * SPLIT + ks) * 3072 + row2) * 32 + s4];
            x1.x += a.x; x1.y += a.y; x1.z += a.z; x1.w += a.w;
            x2.x += c.x; x2.y += c.y; x2.z += c.z; x2.w += c.w;
        }
        float invf = powf(10000.0f, -(float)i / 64.0f);
        float y1[4], y2[4];
        const float* e1 = (const float*)&x1;
        const float* e2 = (const float*)&x2;
        #pragma unroll
        for (int e = 0; e < 4; e++) {
            int s = s4 * 4 + e;
            float pos = (float)positions[b * SEQ + s];
            float sn, cs;
            sincosf(pos * invf, &sn, &cs);
            y1[e] = e1[e] * cs - e2[e] * sn;
            y2[e] = e2[e] * cs + e1[e] * sn;
        }
        out[orow * 32 + s4] = make_float4(y1[0], y1[1], y1[2], y1[3]);
        out[(orow + 64) * 32 + s4] = make_float4(y2[0], y2[1], y2[2], y2[3]);
    } else {
        int j = idx - nA;
        int s4 = j & 31;
        int row = (j >> 5) % 512;
        int b = j / (512 * 32);
        float4 s = {0.f, 0.f, 0.f, 0.f};
        #pragma unroll 1
        for (int ks = 0; ks < SPLIT; ks++) {
            float4 a = p4[((long)(b * SPLIT + ks) * 3072 + 2560 + row) * 32 + s4];
            s.x += a.x; s.y += a.y; s.z += a.z; s.w += a.w;
        }
        ((float4*)v)[((long)b * 512 + row) * 32 + s4] = s;
    }
}

// ---------------- fused cq reduce + RoPE (SPLIT=8) ----------------
__global__ void reduce_rope_q(const float* __restrict__ part, float* __restrict__ q,
                              const int* __restrict__ positions) {
    const int SPLIT = 8;
    int idx = blockIdx.x * blockDim.x + threadIdx.x;
    if (idx >= NB * 16 * 64 * 32) return;
    int s4 = idx & 31;
    int i  = (idx >> 5) & 63;
    int h  = (idx >> 11) & 15;
    int b  = idx >> 15;
    int row1 = h * 128 + i;
    int row2 = row1 + 64;
    const float4* p4 = (const float4*)part;

    float4 x1 = {0.f, 0.f, 0.f, 0.f}, x2 = {0.f, 0.f, 0.f, 0.f};
    #pragma unroll 1
    for (int ks = 0; ks < SPLIT; ks++) {
        float4 a = p4[((long)(b * SPLIT + ks) * 2048 + row1) * 32 + s4];
        float4 c = p4[((long)(b * SPLIT + ks) * 2048 + row2) * 32 + s4];
        x1.x += a.x; x1.y += a.y; x1.z += a.z; x1.w += a.w;
        x2.x += c.x; x2.y += c.y; x2.z += c.z; x2.w += c.w;
    }
    float invf = powf(10000.0f, -(float)i / 64.0f);
    float y1[4], y2[4];
    const float* e1 = (const float*)&x1;
    const float* e2 = (const float*)&x2;
    #pragma unroll
    for (int e = 0; e < 4; e++) {
        int s = s4 * 4 + e;
        float pos = (float)positions[b * SEQ + s];
        float sn, cs;
        sincosf(pos * invf, &sn, &cs);
        y1[e] = e1[e] * cs - e2[e] * sn;
        y2[e] = e2[e] * cs + e1[e] * sn;
    }
    float4* out = (float4*)q;
    long orow = (long)b * 2048 + row1;
    out[orow * 32 + s4] = make_float4(y1[0], y1[1], y1[2], y1[3]);
    out[(orow + 64) * 32 + s4] = make_float4(y2[0], y2[1], y2[2], y2[3]);
}

// ---------------- RMSNorm (optionally also copying src into xkeep) ----------------
__global__ void rmsnorm_kernel(const float* __restrict__ x, const float* __restrict__ w,
                               float* __restrict__ out, float* __restrict__ xkeep) {
    int s = blockIdx.x * 32 + threadIdx.x;
    int b = blockIdx.y;
    const float* xb = x + (long)b * DIM * SEQ;
    float* ob = out + (long)b * DIM * SEQ;
    float* kb = xkeep ? xkeep + (long)b * DIM * SEQ : 0;
    float ss = 0.0f;
    for (int d = threadIdx.y; d < DIM; d += 8) {
        float v = xb[d * SEQ + s];
        if (kb) kb[d * SEQ + s] = v;
        ss += v * v;
    }
    __shared__ float red[8][33];
    red[threadIdx.y][threadIdx.x] = ss;
    __syncthreads();
    if (threadIdx.y == 0) {
        float tot = 0.0f;
        #pragma unroll
        for (int i = 0; i < 8; i++) tot += red[i][threadIdx.x];
        red[0][threadIdx.x] = rsqrtf(tot / (float)DIM + EPSV);
    }
    __syncthreads();
    float inv = red[0][threadIdx.x];
    for (int d = threadIdx.y; d < DIM; d += 8) {
        ob[d * SEQ + s] = xb[d * SEQ + s] * inv * w[d];
    }
}

// ---------------- merge k,v into scratch; constant-divisor indexing + window skip ----------------
__global__ void update_kv(const float* __restrict__ kc, const float* __restrict__ knew,
                          float* __restrict__ keybuf,
                          const float* __restrict__ vc, const float* __restrict__ vnew,
                          float* __restrict__ valbuf, const int* __restrict__ wptr) {
    int idx = blockIdx.x * blockDim.x + threadIdx.x;
    const int total = NB * HKVN * ALEN * HDN;
    if (idx >= total * 2) return;
    int w = wptr[0];
    int aLim = w + SEQ; if (aLim > ALEN) aLim = ALEN;
    int aCopy = (aLim + 127) & ~127; if (aCopy > ALEN) aCopy = ALEN;
    if (idx < total) {
        int d = idx % HDN;
        int a = (idx / HDN) % ALEN;
        if (a >= aCopy) return;
        int kh = (idx / (HDN * ALEN)) % HKVN;
        int b = idx / (HDN * ALEN * HKVN);
        float v;
        if (a >= w && a < w + SEQ) {
            v = knew[(((long)b * HKVN + kh) * HDN + d) * SEQ + (a - w)];
        } else {
            v = kc[idx];
        }
        keybuf[idx] = v;
    } else {
        int i = idx - total;
        int a = i % ALEN;
        if (a >= aCopy) return;
        int d = (i / ALEN) % HDN;
        int kh = (i / (ALEN * HDN)) % HKVN;
        int b = i / (ALEN * HDN * HKVN);
        float v;
        if (a >= w && a < w + SEQ) {
            v = vnew[(((long)b * HKVN + kh) * HDN + d) * SEQ + (a - w)];
        } else {
            v = vc[i];
        }
        valbuf[i] = v;
    }
}

// ---------------- self-attn softmax with window limit ----------------
__global__ void sa_softmax(float* __restrict__ sc, const int* __restrict__ wptr, float scale) {
    int s = blockIdx.x * 32 + threadIdx.x;
    int z = blockIdx.y;
    int w = wptr[0];
    int aLim = w + SEQ; if (aLim > ALEN) aLim = ALEN;
    int aZ = (aLim + 15) & ~15; if (aZ > ALEN) aZ = ALEN;
    float* p = sc + (long)z * ALEN * SEQ;
    __shared__ float red[8][33];

    float mx = -3.0e38f;
    for (int a = threadIdx.y; a < aLim; a += 8) {
        float v = p[(long)a * SEQ + s] * scale;
        if (a > w + s) v += NEGV;
        p[(long)a * SEQ + s] = v;
        mx = fmaxf(mx, v);
    }
    red[threadIdx.y][threadIdx.x] = mx;
    __syncthreads();
    if (threadIdx.y == 0) {
        float m = red[0][threadIdx.x];
        #pragma unroll
        for (int i = 1; i < 8; i++) m = fmaxf(m, red[i][threadIdx.x]);
        red[0][threadIdx.x] = m;
    }
    __syncthreads();
    mx = red[0][threadIdx.x];
    __syncthreads();

    float sum = 0.0f;
    for (int a = threadIdx.y; a < aLim; a += 8) {
        float e = expf(p[(long)a * SEQ + s] - mx);
        p[(long)a * SEQ + s] = e;
        sum += e;
    }
    red[threadIdx.y][threadIdx.x] = sum;
    __syncthreads();
    if (threadIdx.y == 0) {
        float t = red[0][threadIdx.x];
        #pragma unroll
        for (int i = 1; i < 8; i++) t += red[i][threadIdx.x];
        red[0][threadIdx.x] = 1.0f / t;
    }
    __syncthreads();
    float rinv = red[0][threadIdx.x];
    for (int a = threadIdx.y; a < aLim; a += 8) {
        p[(long)a * SEQ + s] *= rinv;
    }
    for (int a = aLim + threadIdx.y; a < aZ; a += 8) {
        p[(long)a * SEQ + s] = 0.0f;
    }
}

// ---------------- cross-attn softmax with length limit ----------------
__global__ void ca_softmax(float* __restrict__ sc, const int* __restrict__ enc, float scale) {
    int s = blockIdx.x * 32 + threadIdx.x;
    int z = blockIdx.y;
    int b = z / HCN;
    int len = enc[b]; if (len > TLEN) len = TLEN;
    int tZ = (len + 15) & ~15; if (tZ > TLEN) tZ = TLEN;
    float* p = sc + (long)z * TLEN * SEQ;
    __shared__ float red[8][33];

    float mx = -3.0e38f;
    for (int t = threadIdx.y; t < len; t += 8) {
        float v = p[(long)t * SEQ + s] * scale;
        p[(long)t * SEQ + s] = v;
        mx = fmaxf(mx, v);
    }
    red[threadIdx.y][threadIdx.x] = mx;
    __syncthreads();
    if (threadIdx.y == 0) {
        float m = red[0][threadIdx.x];
        #pragma unroll
        for (int i = 1; i < 8; i++) m = fmaxf(m, red[i][threadIdx.x]);
        red[0][threadIdx.x] = m;
    }
    __syncthreads();
    mx = red[0][threadIdx.x];
    __syncthreads();

    float sum = 0.0f;
    for (int t = threadIdx.y; t < len; t += 8) {
        float e = expf(p[(long)t * SEQ + s] - mx);
        p[(long)t * SEQ + s] = e;
        sum += e;
    }
    red[threadIdx.y][threadIdx.x] = sum;
    __syncthreads();
    if (threadIdx.y == 0) {
        float t = red[0][threadIdx.x];
        #pragma unroll
        for (int i = 1; i < 8; i++) t += red[i][threadIdx.x];
        red[0][threadIdx.x] = 1.0f / t;
    }
    __syncthreads();
    float rinv = red[0][threadIdx.x];
    for (int t = threadIdx.y; t < len; t += 8) {
        p[(long)t * SEQ + s] *= rinv;
    }
    for (int t = len + threadIdx.y; t < tZ; t += 8) {
        p[(long)t * SEQ + s] = 0.0f;
    }
}

__global__ void silu_mul_gu(const float* __restrict__ gu, float* __restrict__ out) {
    int i = blockIdx.x * blockDim.x + threadIdx.x;
    const int per = FFN * SEQ;
    if (i >= NB * per) return;
    int b = i / per, r = i % per;
    float g = gu[(long)b * 2 * per + r];
    float u = gu[(long)b * 2 * per + per + r];
    out[i] = (g / (1.0f + expf(-g))) * u;
}

// ---------------- host orchestration ----------------
extern "C" void kernel_launch(void* const* d_in, const int* in_sizes, int n_in,
                              void* d_out, int out_size) {
    const float* x_in     = (const float*)d_in[0];
    const int*   positions= (const int*)d_in[1];
    const int*   kvw      = (const int*)d_in[2];
    const int*   enc_len  = (const int*)d_in[4];
    const float* q_w      = (const float*)d_in[5];
    const float* k_w      = (const float*)d_in[6];
    const float* v_w      = (const float*)d_in[7];
    const float* o_w      = (const float*)d_in[8];
    const float* cq_w     = (const float*)d_in[9];
    const float* co_w     = (const float*)d_in[10];
    const float* sa_norm  = (const float*)d_in[11];
    const float* ca_norm  = (const float*)d_in[12];
    const float* mlp_norm = (const float*)d_in[13];
    const float* fin_norm = (const float*)d_in[14];
    const float* wg_w     = (const float*)d_in[15];
    const float* wu_w     = (const float*)d_in[16];
    const float* wd_w     = (const float*)d_in[17];
    const float* k_cache  = (const float*)d_in[18];
    const float* v_cache  = (const float*)d_in[19];
    const float* ck_cache = (const float*)d_in[20];
    const float* cv_cache = (const float*)d_in[21];

    float *px, *ph, *pq, *pk, *pv, *pkey, *pval, *psc, *pattn, *pcsc, *pgu, *pgate, *ppart;
    cudaGetSymbolAddress((void**)&px,    g_x);
    cudaGetSymbolAddress((void**)&ph,    g_h);
    cudaGetSymbolAddress((void**)&pq,    g_q);
    cudaGetSymbolAddress((void**)&pk,    g_k);
    cudaGetSymbolAddress((void**)&pv,    g_v);
    cudaGetSymbolAddress((void**)&pkey,  g_key);
    cudaGetSymbolAddress((void**)&pval,  g_val);
    cudaGetSymbolAddress((void**)&psc,   g_scores);
    cudaGetSymbolAddress((void**)&pattn, g_attn);
    cudaGetSymbolAddress((void**)&pcsc,  g_cscores);
    cudaGetSymbolAddress((void**)&pgu,   g_gu);
    cudaGetSymbolAddress((void**)&pgate, g_gate);
    cudaGetSymbolAddress((void**)&ppart, g_part);

    const float scale = 0.08838834764831845f;  // 1/sqrt(128)
    dim3 blk328(32, 8);

    for (int l = 0; l < NLAYER; l++) {
        long wOffD2  = (long)l * DIM * DIM;
        long wOffKV  = (long)l * DIM * (HKVN * HDN);
        long wOffFF  = (long)l * DIM * FFN;
        long wOffFFd = (long)l * FFN * DIM;
        long cOffK   = (long)l * NB * HCN * TLEN * HDCN;
        long cOffV   = (long)l * NB * HCN * HDCN * TLEN;

        // ---- self attention ----
        if (l == 0) {
            rmsnorm_kernel<<<dim3(SEQ / 32, NB), blk328>>>(x_in, sa_norm, ph, px);
        } else {
            rmsnorm_kernel<<<dim3(SEQ / 32, NB), blk328>>>(px, sa_norm + (long)l * DIM, ph, (float*)0);
        }

        // fused qkv: M=3072, split=4 -> 192 CTAs -> partials; fused reduce+rope
        gemm_mma_multi<<<dim3(24, 4, NB), 256>>>(
            q_w + wOffD2, 2048, 2048,
            k_w + wOffKV, 512, 2560,
            v_w + wOffKV, 512,
            ph, (float*)0, DIM, 3072, SEQ, (long)DIM * SEQ, 0, ppart);
        {
            int n = NB * 20 * 64 * 32 + NB * 512 * 32;
            reduce_qkv_rope<<<(n + 255) / 256, 256>>>(ppart, pq, pk, pv, positions);
        }
        {
            int n = 2 * NB * HKVN * ALEN * HDN;
            update_kv<<<(n + 255) / 256, 256>>>(
                k_cache + (long)l * NB * HKVN * ALEN * HDN, pk, pkey,
                v_cache + (long)l * NB * HKVN * HDN * ALEN, pv, pval, kvw);
        }

        // scores: NN split=1, skip fully-masked row tiles (mode 1)
        gemm_mma<<<dim3(12, 1, NB * HQN), 256>>>(pkey, pq, psc,
            HDN, ALEN, HDN, SEQ, SEQ, (long)ALEN * HDN, GRP, (long)HDN * SEQ, (long)ALEN * SEQ,
            0, 0, 1, ppart, kvw, 1);

        sa_softmax<<<dim3(SEQ / 32, NB * HQN), blk328>>>(psc, kvw, scale);

        // attn = val @ probs: split=16, K-clamped (mode 3)
        gemm_mma<<<dim3(1, 16, NB * HQN), 256>>>(pval, psc, pattn,
            ALEN, HDN, ALEN, SEQ, SEQ, (long)HDN * ALEN, GRP, (long)ALEN * SEQ, 0,
            0, 0, 16, ppart, kvw, 3);
        reduce_split<<<(32 * 128 * 128 / 4 + 255) / 256, 256>>>(ppart, pattn, 128L * 128, 16, 0, 32L * 128 * 128,
            kvw, 3, ALEN / 16);

        // o: split=8 -> 256 CTAs (full occ-2 wave)
        gemm_mma<<<dim3(16, 8, NB), 256>>>(o_w + wOffD2, pattn, px,
            HQN * HDN, DIM, DIM, SEQ, SEQ, 0, 1, (long)HQN * HDN * SEQ, 0, 0, 1, 8, ppart, kvw, 0);
        reduce_split<<<(NB * 2048 * 128 / 4 + 255) / 256, 256>>>(ppart, px, 2048L * 128, 8, 1, (long)NB * 2048 * 128,
            kvw, 0, 0);

        // ---- cross attention ----
        rmsnorm_kernel<<<dim3(SEQ / 32, NB), blk328>>>(px, ca_norm + (long)l * DIM, ph, (float*)0);

        // cq: split=8 -> partials; fused reduce+rope
        gemm_mma<<<dim3(16, 8, NB), 256>>>(cq_w + wOffD2, ph, pq,
            DIM, 2048, 2048, SEQ, SEQ, 0, 1, (long)DIM * SEQ, 0, 0, 1, 8, ppart, kvw, 0);
        {
            int n = NB * 16 * 64 * 32;
            reduce_rope_q<<<(n + 255) / 256, 256>>>(ppart, pq, positions);
        }

        // cscores: skip tiles beyond encoder length (mode 2)
        gemm_mma<<<dim3(4, 1, NB * HCN), 256>>>(ck_cache + cOffK, pq, pcsc,
            HDCN, TLEN, HDCN, SEQ, SEQ, (long)TLEN * HDCN, 1, (long)HDCN * SEQ, (long)TLEN * SEQ,
            0, 0, 1, ppart, enc_len, 2);

        ca_softmax<<<dim3(SEQ / 32, NB * HCN), blk328>>>(pcsc, enc_len, scale);

        // cattn: K-clamped at encoder length (mode 4)
        gemm_mma<<<dim3(1, 8, NB * HCN), 256>>>(cv_cache + cOffV, pcsc, pattn,
            TLEN, HDCN, TLEN, SEQ, SEQ, (long)HDCN * TLEN, 1, (long)TLEN * SEQ, 0,
            0, 0, 8, ppart, enc_len, 4);
        reduce_split<<<(32 * 128 * 128 / 4 + 255) / 256, 256>>>(ppart, pattn, 128L * 128, 8, 0, 32L * 128 * 128,
            enc_len, 4, TLEN / 8);

        // co: split=8
        gemm_mma<<<dim3(16, 8, NB), 256>>>(co_w + wOffD2, pattn, px,
            HCN * HDCN, DIM, DIM, SEQ, SEQ, 0, 1, (long)HCN * HDCN * SEQ, 0, 0, 1, 8, ppart, kvw, 0);
        reduce_split<<<(NB * 2048 * 128 / 4 + 255) / 256, 256>>>(ppart, px, 2048L * 128, 8, 1, (long)NB * 2048 * 128,
            kvw, 0, 0);

        // ---- MLP ----
        rmsnorm_kernel<<<dim3(SEQ / 32, NB), blk328>>>(px, mlp_norm + (long)l * DIM, ph, (float*)0);

        // fused gate+up: M=16384, split=1 -> 256 CTAs, DIRECT write
        gemm_mma_multi<<<dim3(128, 1, NB), 256>>>(
            wg_w + wOffFF, FFN, FFN,
            wu_w + wOffFF, FFN, 2 * FFN,
            wu_w + wOffFF, FFN,
            ph, pgu, DIM, 2 * FFN, SEQ, (long)DIM * SEQ, (long)2 * FFN * SEQ, ppart);
        {
            int n = NB * FFN * SEQ;
            silu_mul_gu<<<(n + 255) / 256, 256>>>(pgu, pgate);
        }
        // down: split=8 -> 256 CTAs
        gemm_mma<<<dim3(16, 8, NB), 256>>>(wd_w + wOffFFd, pgate, px,
            FFN, DIM, DIM, SEQ, SEQ, 0, 1, (long)FFN * SEQ, 0, 0, 1, 8, ppart, kvw, 0);
        reduce_split<<<(NB * 2048 * 128 / 4 + 255) / 256, 256>>>(ppart, px, 2048L * 128, 8, 1, (long)NB * 2048 * 128,
            kvw, 0, 0);
    }

    rmsnorm_kernel<<<dim3(SEQ / 32, NB), blk328>>>(px, fin_norm, (float*)d_out, (float*)0);
}